// round 15
// baseline (speedup 1.0000x reference)
#include <cuda_runtime.h>
#include <cuda_bf16.h>
#include <math.h>
#include <stdint.h>

#define NN 50000
#define NE 800000
#define HDIM 64
#define NBLK 196   // csr kernel grid; all blocks co-resident (196 < 148*2)

#define EI_OFF  3200000LL
#define AL_OFF  4800000LL

// ---------------- scratch (static device globals; no allocation) ----------------
// g_deg is zero at load and re-zeroed by k_node each call -> identical work every call.
__device__ int   g_src[NE];
__device__ int   g_dst[NE];
__device__ int   g_deg[NN];
__device__ int   g_rowstart[NN + 1];
__device__ int   g_cursor[NN];
__device__ int   g_elist[NE];
__device__ int   g_part[256];
__device__ float g_xl[NN * HDIM];
__device__ float g_xr[NN * HDIM];
__device__ float g_res[NN * HDIM];
__device__ float g_score[NE * 4];       // only for rare deg>128 fallback
__device__ unsigned g_cnt;              // grid-barrier arrival counter (self-resetting)
__device__ unsigned g_gen;              // grid-barrier generation (monotonic)

// ---------------- K0: convert (+int64 detect) + degree histogram + ei passthrough ----------------
__global__ void k_convert(const int* __restrict__ ei, float* __restrict__ out, int write_ei) {
    __shared__ int s64;
    if (threadIdx.x == 0) {
        int f = 1;
#pragma unroll
        for (int i = 0; i < 16; i++) f &= (ei[2 * i + 1] == 0);
        s64 = f;
    }
    __syncthreads();
    int is64 = s64;
    int e = blockIdx.x * blockDim.x + threadIdx.x;
    if (e < NE) {
        int s, d;
        if (is64) {
            s = ei[2 * e];
            d = ei[2 * (NE + e)];
        } else {
            s = ei[e];
            d = ei[NE + e];
        }
        g_src[e] = s;
        g_dst[e] = d;
        atomicAdd(&g_deg[d], 1);
        if (write_ei) {
            out[EI_OFF + e]      = (float)s;
            out[EI_OFF + NE + e] = (float)d;
        }
    }
}

// ---------------- K1a: projections Wl,Wr only (gates k_node) — exact R8 form ----------------
// 128 threads = 4 warps: mat = warp&1 (0=Wl,1=Wr), rh = warp>>1 (16 rows each).
__global__ void __launch_bounds__(128) k_proj2(
    const float* __restrict__ x,
    const float* __restrict__ Wl, const float* __restrict__ bl,
    const float* __restrict__ Wr, const float* __restrict__ br)
{
    __shared__ __align__(16) float sx[128 * 32];  // [k][r]
    int tid = threadIdx.x;
    int lane = tid & 31;
    int warp = tid >> 5;
    int row0 = blockIdx.x * 32;
    const float4* x4 = reinterpret_cast<const float4*>(x);
    for (int idx = tid; idx < 1024; idx += 128) {
        int r = idx & 31, c4 = idx >> 5;
        int row = row0 + r;
        float4 v = make_float4(0.f, 0.f, 0.f, 0.f);
        if (row < NN) v = x4[row * 32 + c4];
        int k = c4 * 4;
        sx[(k + 0) * 32 + r] = v.x;
        sx[(k + 1) * 32 + r] = v.y;
        sx[(k + 2) * 32 + r] = v.z;
        sx[(k + 3) * 32 + r] = v.w;
    }
    __syncthreads();

    int mat = warp & 1;
    int rh  = warp >> 1;
    const float* W = mat ? Wr : Wl;
    const float* B = mat ? br : bl;
    float* Out = mat ? g_xr : g_xl;
    int j0 = lane, j1 = lane + 32;

    unsigned long long acc0[8], acc1[8];
#pragma unroll
    for (int i = 0; i < 8; i++) { acc0[i] = 0ULL; acc1[i] = 0ULL; }

#pragma unroll 2
    for (int k = 0; k < 128; k++) {
        float w0 = W[k * 64 + j0];
        float w1 = W[k * 64 + j1];
        unsigned long long wd0, wd1;
        asm("mov.b64 %0, {%1, %2};" : "=l"(wd0) : "f"(w0), "f"(w0));
        asm("mov.b64 %0, {%1, %2};" : "=l"(wd1) : "f"(w1), "f"(w1));
        const ulonglong2* xp =
            reinterpret_cast<const ulonglong2*>(&sx[k * 32 + rh * 16]);
#pragma unroll
        for (int rq = 0; rq < 4; rq++) {
            ulonglong2 xv = xp[rq];
            asm("fma.rn.f32x2 %0, %1, %2, %0;" : "+l"(acc0[2*rq])   : "l"(xv.x), "l"(wd0));
            asm("fma.rn.f32x2 %0, %1, %2, %0;" : "+l"(acc1[2*rq])   : "l"(xv.x), "l"(wd1));
            asm("fma.rn.f32x2 %0, %1, %2, %0;" : "+l"(acc0[2*rq+1]) : "l"(xv.y), "l"(wd0));
            asm("fma.rn.f32x2 %0, %1, %2, %0;" : "+l"(acc1[2*rq+1]) : "l"(xv.y), "l"(wd1));
        }
    }

    float b0 = B[j0], b1 = B[j1];
#pragma unroll
    for (int rp = 0; rp < 8; rp++) {
        int row = row0 + rh * 16 + 2 * rp;
        float lo0 = __uint_as_float((unsigned)(acc0[rp] & 0xffffffffULL)) + b0;
        float hi0 = __uint_as_float((unsigned)(acc0[rp] >> 32)) + b0;
        float lo1 = __uint_as_float((unsigned)(acc1[rp] & 0xffffffffULL)) + b1;
        float hi1 = __uint_as_float((unsigned)(acc1[rp] >> 32)) + b1;
        if (row < NN)     { Out[row * 64 + j0] = lo0; Out[row * 64 + j1] = lo1; }
        if (row + 1 < NN) { Out[(row + 1) * 64 + j0] = hi0; Out[(row + 1) * 64 + j1] = hi1; }
    }
}

// ---------------- K1b: residual projection Wres (overlaps k_node) ----------------
__global__ void __launch_bounds__(64) k_res(
    const float* __restrict__ x,
    const float* __restrict__ Wres, const float* __restrict__ bres)
{
    __shared__ __align__(16) float sx[128 * 32];
    int tid = threadIdx.x;
    int lane = tid & 31;
    int rh = tid >> 5;
    int row0 = blockIdx.x * 32;
    const float4* x4 = reinterpret_cast<const float4*>(x);
    for (int idx = tid; idx < 1024; idx += 64) {
        int r = idx & 31, c4 = idx >> 5;
        int row = row0 + r;
        float4 v = make_float4(0.f, 0.f, 0.f, 0.f);
        if (row < NN) v = x4[row * 32 + c4];
        int k = c4 * 4;
        sx[(k + 0) * 32 + r] = v.x;
        sx[(k + 1) * 32 + r] = v.y;
        sx[(k + 2) * 32 + r] = v.z;
        sx[(k + 3) * 32 + r] = v.w;
    }
    __syncthreads();

    int j0 = lane, j1 = lane + 32;
    unsigned long long acc0[8], acc1[8];
#pragma unroll
    for (int i = 0; i < 8; i++) { acc0[i] = 0ULL; acc1[i] = 0ULL; }

#pragma unroll 2
    for (int k = 0; k < 128; k++) {
        float w0 = Wres[k * 64 + j0];
        float w1 = Wres[k * 64 + j1];
        unsigned long long wd0, wd1;
        asm("mov.b64 %0, {%1, %2};" : "=l"(wd0) : "f"(w0), "f"(w0));
        asm("mov.b64 %0, {%1, %2};" : "=l"(wd1) : "f"(w1), "f"(w1));
        const ulonglong2* xp =
            reinterpret_cast<const ulonglong2*>(&sx[k * 32 + rh * 16]);
#pragma unroll
        for (int rq = 0; rq < 4; rq++) {
            ulonglong2 xv = xp[rq];
            asm("fma.rn.f32x2 %0, %1, %2, %0;" : "+l"(acc0[2*rq])   : "l"(xv.x), "l"(wd0));
            asm("fma.rn.f32x2 %0, %1, %2, %0;" : "+l"(acc1[2*rq])   : "l"(xv.x), "l"(wd1));
            asm("fma.rn.f32x2 %0, %1, %2, %0;" : "+l"(acc0[2*rq+1]) : "l"(xv.y), "l"(wd0));
            asm("fma.rn.f32x2 %0, %1, %2, %0;" : "+l"(acc1[2*rq+1]) : "l"(xv.y), "l"(wd1));
        }
    }

    float b0 = bres[j0], b1 = bres[j1];
#pragma unroll
    for (int rp = 0; rp < 8; rp++) {
        int row = row0 + rh * 16 + 2 * rp;
        float lo0 = __uint_as_float((unsigned)(acc0[rp] & 0xffffffffULL)) + b0;
        float hi0 = __uint_as_float((unsigned)(acc0[rp] >> 32)) + b0;
        float lo1 = __uint_as_float((unsigned)(acc1[rp] & 0xffffffffULL)) + b1;
        float hi1 = __uint_as_float((unsigned)(acc1[rp] >> 32)) + b1;
        if (row < NN)     { g_res[row * 64 + j0] = lo0; g_res[row * 64 + j1] = lo1; }
        if (row + 1 < NN) { g_res[(row + 1) * 64 + j0] = hi0; g_res[(row + 1) * 64 + j1] = hi1; }
    }
}

// ---------------- grid-wide barrier ----------------
__device__ __forceinline__ void gsync() {
    __threadfence();
    __syncthreads();
    if (threadIdx.x == 0) {
        unsigned gen = atomicAdd(&g_gen, 0u);
        if (atomicInc(&g_cnt, NBLK - 1u) == NBLK - 1u) {
            atomicAdd(&g_gen, 1u);
        } else {
            while (atomicAdd(&g_gen, 0u) == gen) { }
        }
    }
    __syncthreads();
}

// ---------------- K2: fused CSR build ----------------
__global__ void __launch_bounds__(256) k_csr() {
    __shared__ int s[256];
    __shared__ int sp[256];
    int t = threadIdx.x;
    int b = blockIdx.x;
    int idx = b * 256 + t;
    int v = (idx < NN) ? g_deg[idx] : 0;

    s[t] = v;
    __syncthreads();
#pragma unroll
    for (int off = 128; off > 0; off >>= 1) {
        if (t < off) s[t] += s[t + off];
        __syncthreads();
    }
    if (t == 0) g_part[b] = s[0];
    gsync();

    sp[t] = (t < NBLK) ? g_part[t] : 0;
    s[t] = v;
    __syncthreads();
#pragma unroll
    for (int off = 1; off < 256; off <<= 1) {
        int u1 = (t >= off) ? sp[t - off] : 0;
        int u2 = (t >= off) ? s[t - off] : 0;
        __syncthreads();
        sp[t] += u1;
        s[t]  += u2;
        __syncthreads();
    }
    int blk_off = (b == 0) ? 0 : sp[b - 1];
    int excl = s[t] - v + blk_off;
    if (idx < NN) {
        g_rowstart[idx] = excl;
        g_cursor[idx]   = excl;
    }
    if (b == 0 && t == 0) g_rowstart[NN] = sp[NBLK - 1];
    gsync();

    for (int e = b * 256 + t; e < NE; e += NBLK * 256) {
        int d = g_dst[e];
        int pos = atomicAdd(&g_cursor[d], 1);
        g_elist[pos] = e;
    }
}

// ---------------- K3: per-node kernel — R8 body + unroll-2 (ONLY diff vs R8) ----------------
// Warp per node. lane = eslot*8 + h*2 + half: 4 edge slots x 4 heads x 2 dim-halves.
__global__ void __launch_bounds__(128) k_node(
    const float* __restrict__ edge_attr,
    const float* __restrict__ We,
    const float* __restrict__ att,
    const float* __restrict__ bias_out,
    float* __restrict__ out, int do_alpha)
{
    __shared__ int sbuf[4 * 128];
    __shared__ __align__(16) float ssc[4][128 * 4];
    __shared__ __align__(16) float sacc[4][64];
    __shared__ __align__(16) float sWA[160];   // We at [h*20+j], att at [80+h*20+j]
    int tid = threadIdx.x;
    int warp = tid >> 5;
    int lane = tid & 31;

    if (tid < 64) {
        int hh = tid >> 4, jj = tid & 15;
        sWA[hh * 20 + jj] = We[tid];
    } else {
        int u = tid - 64;
        int hh = u >> 4, jj = u & 15;
        sWA[80 + hh * 20 + jj] = att[u];
    }
    __syncthreads();

    int n = blockIdx.x * 4 + warp;    // NN % 4 == 0
    int* buf = &sbuf[warp * 128];
    float* psc = ssc[warp];

    int start = g_rowstart[n];
    int deg = g_rowstart[n + 1] - start;

    // deterministic: sort this node's edge ids ascending (fixed 32-iter rank loop)
    if (deg <= 32) {
        int myid = (lane < deg) ? g_elist[start + lane] : 0x7fffffff;
        int rank = 0;
#pragma unroll
        for (int j = 0; j < 32; j++) {
            int o = __shfl_sync(0xffffffffu, myid, j);
            rank += (o < myid);
        }
        if (lane < deg) buf[rank] = myid;
    } else {
        int dd = min(deg, 128);
        for (int i = lane; i < dd; i += 32) {
            int vv = g_elist[start + i];
            int rank = 0;
            for (int j = 0; j < dd; j++) rank += (g_elist[start + j] < vv);
            buf[rank] = vv;
        }
    }
    __syncwarp();
    bool use_buf = (deg <= 128);

    int eslot = lane >> 3;          // 0..3
    int h     = (lane >> 1) & 3;    // 0..3
    int half  = lane & 1;           // 0..1
    int dbase = h * 16 + half * 8;  // this lane's 8-dim slice

    const float4* xrp = (const float4*)&g_xr[n * 64 + dbase];
    float4 xr0 = xrp[0], xr1 = xrp[1];
    const float4* pWe = (const float4*)&sWA[h * 20 + half * 8];
    const float4* pAt = (const float4*)&sWA[80 + h * 20 + half * 8];

    const float NEG_INF = __int_as_float(0xff800000);
    float m = NEG_INF;
    float den = 0.f;
    float acc[8];
#pragma unroll
    for (int j = 0; j < 8; j++) acc[j] = 0.f;

#pragma unroll 2
    for (int base = 0; base < deg; base += 4) {
        int ei = base + eslot;
        bool act = (ei < deg);
        int e = 0, s = 0;
        float ea = 0.f;
        if (act) {
            e = use_buf ? buf[ei] : g_elist[start + ei];
            s = g_src[e];
            ea = edge_attr[e];
        }
        const float4* xlp = (const float4*)&g_xl[s * 64 + dbase];
        float4 a0 = xlp[0], a1 = xlp[1];

        float p;
        {
#define LRELU(v) (fmaxf((v), 0.f) + 0.2f * fminf((v), 0.f))
            float f;
            float4 w = pWe[0], tt = pAt[0];
            f = fmaf(ea, w.x, a0.x + xr0.x); p = tt.x * LRELU(f);
            f = fmaf(ea, w.y, a0.y + xr0.y); p = fmaf(tt.y, LRELU(f), p);
            f = fmaf(ea, w.z, a0.z + xr0.z); p = fmaf(tt.z, LRELU(f), p);
            f = fmaf(ea, w.w, a0.w + xr0.w); p = fmaf(tt.w, LRELU(f), p);
            w = pWe[1]; tt = pAt[1];
            f = fmaf(ea, w.x, a1.x + xr1.x); p = fmaf(tt.x, LRELU(f), p);
            f = fmaf(ea, w.y, a1.y + xr1.y); p = fmaf(tt.y, LRELU(f), p);
            f = fmaf(ea, w.z, a1.z + xr1.z); p = fmaf(tt.z, LRELU(f), p);
            f = fmaf(ea, w.w, a1.w + xr1.w); p = fmaf(tt.w, LRELU(f), p);
#undef LRELU
        }
        p += __shfl_xor_sync(0xffffffffu, p, 1);   // combine dim-halves
        if (act) {
            if (half == 0) {
                if (use_buf) psc[ei * 4 + h] = p;   // 16 lanes, distinct banks
                else         g_score[(long long)e * 4 + h] = p;
            }
        } else {
            p = NEG_INF;
        }
        // batch max over the 4 edge slots of this (head,half)
        float q = fmaxf(p, __shfl_xor_sync(0xffffffffu, p, 8));
        q = fmaxf(q, __shfl_xor_sync(0xffffffffu, q, 16));
        float mnew = fmaxf(m, q);
        float scale = __expf(m - mnew);             // first batch: exp(-inf)=0
        float ex = act ? __expf(p - mnew) : 0.f;
        den = den * scale + ex;
        acc[0] = fmaf(acc[0], scale, ex * a0.x);
        acc[1] = fmaf(acc[1], scale, ex * a0.y);
        acc[2] = fmaf(acc[2], scale, ex * a0.z);
        acc[3] = fmaf(acc[3], scale, ex * a0.w);
        acc[4] = fmaf(acc[4], scale, ex * a1.x);
        acc[5] = fmaf(acc[5], scale, ex * a1.y);
        acc[6] = fmaf(acc[6], scale, ex * a1.z);
        acc[7] = fmaf(acc[7], scale, ex * a1.w);
        m = mnew;
    }

    // reduce across the 4 edge-slot lanes (fixed tree -> deterministic)
#pragma unroll
    for (int off = 8; off <= 16; off <<= 1) {
        den += __shfl_xor_sync(0xffffffffu, den, off);
#pragma unroll
        for (int j = 0; j < 8; j++)
            acc[j] += __shfl_xor_sync(0xffffffffu, acc[j], off);
    }

    if (eslot == 0) {
#pragma unroll
        for (int j = 0; j < 8; j++) sacc[warp][dbase + j] = acc[j];
    }
    __syncwarp();
    float2 av = *(const float2*)&sacc[warp][lane * 2];

    float deng = __shfl_sync(0xffffffffu, den, (lane >> 3) * 2);
    float dfin = deng + 1e-16f;
    float2 bo2 = *(const float2*)&bias_out[lane * 2];
    float ox = av.x / dfin + bo2.x;
    float oy = av.y / dfin + bo2.y;
    *(float2*)&out[n * 64 + lane * 2] = make_float2(ox, oy);   // pre-activation

    if (lane == 0) g_deg[n] = 0;   // reset for next call

    if (do_alpha) {
        float m0 = __shfl_sync(0xffffffffu, m, 0);
        float m1 = __shfl_sync(0xffffffffu, m, 2);
        float m2 = __shfl_sync(0xffffffffu, m, 4);
        float m3 = __shfl_sync(0xffffffffu, m, 6);
        float d0 = __shfl_sync(0xffffffffu, den, 0) + 1e-16f;
        float d1 = __shfl_sync(0xffffffffu, den, 2) + 1e-16f;
        float d2 = __shfl_sync(0xffffffffu, den, 4) + 1e-16f;
        float d3 = __shfl_sync(0xffffffffu, den, 6) + 1e-16f;
        for (int i = lane; i < deg; i += 32) {
            int e = use_buf ? buf[i] : g_elist[start + i];
            float4 s4 = use_buf ? *(const float4*)&psc[i * 4]
                                : *(const float4*)&g_score[(long long)e * 4];
            float4 a;
            a.x = __expf(s4.x - m0) / d0;
            a.y = __expf(s4.y - m1) / d1;
            a.z = __expf(s4.z - m2) / d2;
            a.w = __expf(s4.w - m3) / d3;
            *(float4*)&out[AL_OFF + (long long)e * 4] = a;
        }
    }
}

// ---------------- K4: residual + ELU epilogue ----------------
__global__ void k_post(float* __restrict__ out) {
    int i = blockIdx.x * blockDim.x + threadIdx.x;
    if (i < NN * HDIM / 4) {
        float4 o = *(const float4*)&out[i * 4];
        float4 r = *(const float4*)&g_res[i * 4];
        float vx = o.x + r.x, vy = o.y + r.y, vz = o.z + r.z, vw = o.w + r.w;
        vx = vx > 0.f ? vx : expm1f(vx);
        vy = vy > 0.f ? vy : expm1f(vy);
        vz = vz > 0.f ? vz : expm1f(vz);
        vw = vw > 0.f ? vw : expm1f(vw);
        *(float4*)&out[i * 4] = make_float4(vx, vy, vz, vw);
    }
}

// ---------------- launch (exact R8 submission order) ----------------
extern "C" void kernel_launch(void* const* d_in, const int* in_sizes, int n_in,
                              void* d_out, int out_size) {
    const float* x         = (const float*)d_in[0];
    const int*   ei        = (const int*)d_in[1];
    const float* edge_attr = (const float*)d_in[2];
    const float* Wl        = (const float*)d_in[3];
    const float* bl        = (const float*)d_in[4];
    const float* Wr        = (const float*)d_in[5];
    const float* br        = (const float*)d_in[6];
    const float* We        = (const float*)d_in[7];
    const float* att       = (const float*)d_in[8];
    const float* bias_out  = (const float*)d_in[9];
    const float* Wres      = (const float*)d_in[10];
    const float* bres      = (const float*)d_in[11];
    float* out = (float*)d_out;

    int write_ei = (out_size >= 4800000);
    int do_alpha = (out_size >= 8000000);

    static cudaStream_t s2 = 0, s3 = 0;
    static cudaEvent_t evA = 0, evB = 0, evC = 0;
    if (!s2) {
        cudaStreamCreateWithFlags(&s2, cudaStreamNonBlocking);
        cudaStreamCreateWithFlags(&s3, cudaStreamNonBlocking);
        cudaEventCreateWithFlags(&evA, cudaEventDisableTiming);
        cudaEventCreateWithFlags(&evB, cudaEventDisableTiming);
        cudaEventCreateWithFlags(&evC, cudaEventDisableTiming);
    }

    cudaEventRecord(evA, 0);
    cudaStreamWaitEvent(s2, evA, 0);
    cudaStreamWaitEvent(s3, evA, 0);

    // s2: xl/xr projections (gate for k_node); s3: residual projection (gate for k_post)
    k_proj2<<<(NN + 31) / 32, 128, 0, s2>>>(x, Wl, bl, Wr, br);
    cudaEventRecord(evB, s2);
    k_res<<<(NN + 31) / 32, 64, 0, s3>>>(x, Wres, bres);
    cudaEventRecord(evC, s3);

    // stream 0: convert -> CSR
    k_convert<<<(NE + 255) / 256, 256>>>(ei, out, write_ei);
    k_csr<<<NBLK, 256>>>();

    // node pass: needs CSR (stream order) + xl/xr
    cudaStreamWaitEvent(0, evB, 0);
    k_node<<<NN / 4, 128>>>(edge_attr, We, att, bias_out, out, do_alpha);

    // epilogue: needs node output + residual projection
    cudaStreamWaitEvent(0, evC, 0);
    k_post<<<(NN * HDIM / 4 + 255) / 256, 256>>>(out);
}

// round 16
// speedup vs baseline: 1.2469x; 1.2469x over previous
#include <cuda_runtime.h>
#include <cuda_bf16.h>
#include <math.h>
#include <stdint.h>

#define NN 50000
#define NE 800000
#define HDIM 64
#define NBLK 196                 // CSR role blocks (must be co-resident)
#define PROJBLK 1563             // ceil(50000/32) projection role blocks
#define FRONTGRID (NBLK + PROJBLK)

#define EI_OFF  3200000LL
#define AL_OFF  4800000LL

// ---------------- scratch (static device globals; no allocation) ----------------
// g_deg is zero at load and re-zeroed by k_node each call -> identical work every call.
__device__ int   g_src[NE];
__device__ int   g_dst[NE];
__device__ int   g_deg[NN];
__device__ int   g_rowstart[NN + 1];
__device__ int   g_cursor[NN];
__device__ int   g_elist[NE];
__device__ int   g_part[256];
__device__ float g_xl[NN * HDIM];
__device__ float g_xr[NN * HDIM];
__device__ float g_res[NN * HDIM];
__device__ float g_score[NE * 4];       // only for rare deg>128 fallback
__device__ unsigned g_cnt;              // barrier arrival counter (CSR blocks only)
__device__ unsigned g_gen;              // barrier generation (monotonic)

// ---------------- barrier among the NBLK CSR-role blocks ----------------
__device__ __forceinline__ void gsync196() {
    __threadfence();
    __syncthreads();
    if (threadIdx.x == 0) {
        unsigned gen = atomicAdd(&g_gen, 0u);
        if (atomicInc(&g_cnt, NBLK - 1u) == NBLK - 1u) {
            atomicAdd(&g_gen, 1u);
        } else {
            while (atomicAdd(&g_gen, 0u) == gen) { }
        }
    }
    __syncthreads();
}

// ---------------- K1: fused front kernel ----------------
// Blocks 0..NBLK-1: convert + hist -> scan -> scatter (CSR build).
// Blocks NBLK..   : 3-GEMM projections (xl, xr, res), 32 rows per block.
__global__ void __launch_bounds__(256) k_front(
    const int* __restrict__ ei,
    const float* __restrict__ x,
    const float* __restrict__ Wl, const float* __restrict__ bl,
    const float* __restrict__ Wr, const float* __restrict__ br,
    const float* __restrict__ Wres, const float* __restrict__ bres,
    float* __restrict__ out, int write_ei)
{
    __shared__ __align__(16) float sx[128 * 32];   // proj tile; CSR aliases ints below
    int tid = threadIdx.x;
    int b = blockIdx.x;

    if (b < NBLK) {
        // ------------- CSR role -------------
        int* s  = (int*)sx;          // [256]
        int* sp = ((int*)sx) + 256;  // [256]
        __shared__ int s64;

        // phase 0: edge convert (+int64 detect) + degree hist + ei passthrough
        if (tid == 0) {
            int f = 1;
#pragma unroll
            for (int i = 0; i < 16; i++) f &= (ei[2 * i + 1] == 0);
            s64 = f;
        }
        __syncthreads();
        int is64 = s64;
        for (int e = b * 256 + tid; e < NE; e += NBLK * 256) {
            int ss, d;
            if (is64) {
                ss = ei[2 * e];
                d = ei[2 * (NE + e)];
            } else {
                ss = ei[e];
                d = ei[NE + e];
            }
            g_src[e] = ss;
            g_dst[e] = d;
            atomicAdd(&g_deg[d], 1);
            if (write_ei) {
                out[EI_OFF + e]      = (float)ss;
                out[EI_OFF + NE + e] = (float)d;
            }
        }
        gsync196();

        int idx = b * 256 + tid;
        int v = (idx < NN) ? g_deg[idx] : 0;

        // phase 1: per-block degree sum
        s[tid] = v;
        __syncthreads();
#pragma unroll
        for (int off = 128; off > 0; off >>= 1) {
            if (tid < off) s[tid] += s[tid + off];
            __syncthreads();
        }
        if (tid == 0) g_part[b] = s[0];
        gsync196();

        // phase 2: scan of partials + local scan
        sp[tid] = (tid < NBLK) ? g_part[tid] : 0;
        s[tid] = v;
        __syncthreads();
#pragma unroll
        for (int off = 1; off < 256; off <<= 1) {
            int u1 = (tid >= off) ? sp[tid - off] : 0;
            int u2 = (tid >= off) ? s[tid - off] : 0;
            __syncthreads();
            sp[tid] += u1;
            s[tid]  += u2;
            __syncthreads();
        }
        int blk_off = (b == 0) ? 0 : sp[b - 1];
        int excl = s[tid] - v + blk_off;
        if (idx < NN) {
            g_rowstart[idx] = excl;
            g_cursor[idx]   = excl;
        }
        if (b == 0 && tid == 0) g_rowstart[NN] = sp[NBLK - 1];
        gsync196();

        // phase 3: scatter edges into CSR
        for (int e = b * 256 + tid; e < NE; e += NBLK * 256) {
            int d = g_dst[e];
            int pos = atomicAdd(&g_cursor[d], 1);
            g_elist[pos] = e;
        }
    } else {
        // ------------- projection role (R2-proven layout, LDS.128 inner loop) -------------
        int pb = b - NBLK;
        int row0 = pb * 32;
        const float4* x4 = reinterpret_cast<const float4*>(x);
        for (int idx = tid; idx < 1024; idx += 256) {
            int r = idx & 31, c4 = idx >> 5;
            int row = row0 + r;
            float4 v = make_float4(0.f, 0.f, 0.f, 0.f);
            if (row < NN) v = x4[row * 32 + c4];
            int k = c4 * 4;
            sx[(k + 0) * 32 + r] = v.x;
            sx[(k + 1) * 32 + r] = v.y;
            sx[(k + 2) * 32 + r] = v.z;
            sx[(k + 3) * 32 + r] = v.w;
        }
        __syncthreads();
        if (tid >= 192) return;   // 6 compute warps

        int lane = tid & 31;
        int warp = tid >> 5;
        int mat = warp % 3;
        int rh  = warp / 3;       // 0/1 -> rows [rh*16, rh*16+16)
        const float* W = (mat == 0) ? Wl : (mat == 1) ? Wr : Wres;
        const float* B = (mat == 0) ? bl : (mat == 1) ? br : bres;
        float* Out = (mat == 0) ? g_xl : (mat == 1) ? g_xr : g_res;
        int j0 = lane, j1 = lane + 32;

        unsigned long long acc0[8], acc1[8];
#pragma unroll
        for (int i = 0; i < 8; i++) { acc0[i] = 0ULL; acc1[i] = 0ULL; }

#pragma unroll 2
        for (int k = 0; k < 128; k++) {
            float w0 = W[k * 64 + j0];
            float w1 = W[k * 64 + j1];
            unsigned long long wd0, wd1;
            asm("mov.b64 %0, {%1, %2};" : "=l"(wd0) : "f"(w0), "f"(w0));
            asm("mov.b64 %0, {%1, %2};" : "=l"(wd1) : "f"(w1), "f"(w1));
            const ulonglong2* xp =
                reinterpret_cast<const ulonglong2*>(&sx[k * 32 + rh * 16]);
#pragma unroll
            for (int rq = 0; rq < 4; rq++) {
                ulonglong2 xv = xp[rq];   // LDS.128 broadcast: 2 row-pairs
                asm("fma.rn.f32x2 %0, %1, %2, %0;" : "+l"(acc0[2*rq])   : "l"(xv.x), "l"(wd0));
                asm("fma.rn.f32x2 %0, %1, %2, %0;" : "+l"(acc1[2*rq])   : "l"(xv.x), "l"(wd1));
                asm("fma.rn.f32x2 %0, %1, %2, %0;" : "+l"(acc0[2*rq+1]) : "l"(xv.y), "l"(wd0));
                asm("fma.rn.f32x2 %0, %1, %2, %0;" : "+l"(acc1[2*rq+1]) : "l"(xv.y), "l"(wd1));
            }
        }

        float b0 = B[j0], b1 = B[j1];
#pragma unroll
        for (int rp = 0; rp < 8; rp++) {
            int row = row0 + rh * 16 + 2 * rp;
            float lo0 = __uint_as_float((unsigned)(acc0[rp] & 0xffffffffULL)) + b0;
            float hi0 = __uint_as_float((unsigned)(acc0[rp] >> 32)) + b0;
            float lo1 = __uint_as_float((unsigned)(acc1[rp] & 0xffffffffULL)) + b1;
            float hi1 = __uint_as_float((unsigned)(acc1[rp] >> 32)) + b1;
            if (row < NN)     { Out[row * 64 + j0] = lo0; Out[row * 64 + j1] = lo1; }
            if (row + 1 < NN) { Out[(row + 1) * 64 + j0] = hi0; Out[(row + 1) * 64 + j1] = hi1; }
        }
    }
}

// ---------------- K2: per-node kernel (measured-88us body + fused residual/ELU) ----------------
// Warp per node. lane = eslot*8 + h*2 + half: 4 edge slots x 4 heads x 2 dim-halves.
__global__ void __launch_bounds__(128) k_node(
    const float* __restrict__ edge_attr,
    const float* __restrict__ We,
    const float* __restrict__ att,
    const float* __restrict__ bias_out,
    float* __restrict__ out, int do_alpha)
{
    __shared__ int sbuf[4 * 128];
    __shared__ __align__(16) float ssc[4][128 * 4];
    __shared__ __align__(16) float sacc[4][64];
    __shared__ __align__(16) float sWA[160];   // We at [h*20+j], att at [80+h*20+j]
    int tid = threadIdx.x;
    int warp = tid >> 5;
    int lane = tid & 31;

    if (tid < 64) {
        int hh = tid >> 4, jj = tid & 15;
        sWA[hh * 20 + jj] = We[tid];
    } else {
        int u = tid - 64;
        int hh = u >> 4, jj = u & 15;
        sWA[80 + hh * 20 + jj] = att[u];
    }
    __syncthreads();

    int n = blockIdx.x * 4 + warp;    // NN % 4 == 0
    int* buf = &sbuf[warp * 128];
    float* psc = ssc[warp];

    int start = g_rowstart[n];
    int deg = g_rowstart[n + 1] - start;

    // deterministic: sort this node's edge ids ascending (fixed 32-iter rank loop)
    if (deg <= 32) {
        int myid = (lane < deg) ? g_elist[start + lane] : 0x7fffffff;
        int rank = 0;
#pragma unroll
        for (int j = 0; j < 32; j++) {
            int o = __shfl_sync(0xffffffffu, myid, j);
            rank += (o < myid);
        }
        if (lane < deg) buf[rank] = myid;
    } else {
        int dd = min(deg, 128);
        for (int i = lane; i < dd; i += 32) {
            int vv = g_elist[start + i];
            int rank = 0;
            for (int j = 0; j < dd; j++) rank += (g_elist[start + j] < vv);
            buf[rank] = vv;
        }
    }
    __syncwarp();
    bool use_buf = (deg <= 128);

    int eslot = lane >> 3;          // 0..3
    int h     = (lane >> 1) & 3;    // 0..3
    int half  = lane & 1;           // 0..1
    int dbase = h * 16 + half * 8;  // this lane's 8-dim slice

    const float4* xrp = (const float4*)&g_xr[n * 64 + dbase];
    float4 xr0 = xrp[0], xr1 = xrp[1];
    const float4* pWe = (const float4*)&sWA[h * 20 + half * 8];
    const float4* pAt = (const float4*)&sWA[80 + h * 20 + half * 8];

    const float NEG_INF = __int_as_float(0xff800000);
    float m = NEG_INF;
    float den = 0.f;
    float acc[8];
#pragma unroll
    for (int j = 0; j < 8; j++) acc[j] = 0.f;

#pragma unroll 2
    for (int base = 0; base < deg; base += 4) {
        int ei = base + eslot;
        bool act = (ei < deg);
        int e = 0, s = 0;
        float ea = 0.f;
        if (act) {
            e = use_buf ? buf[ei] : g_elist[start + ei];
            s = g_src[e];
            ea = edge_attr[e];
        }
        const float4* xlp = (const float4*)&g_xl[s * 64 + dbase];
        float4 a0 = xlp[0], a1 = xlp[1];

        float p;
        {
#define LRELU(v) (fmaxf((v), 0.f) + 0.2f * fminf((v), 0.f))
            float f;
            float4 w = pWe[0], tt = pAt[0];
            f = fmaf(ea, w.x, a0.x + xr0.x); p = tt.x * LRELU(f);
            f = fmaf(ea, w.y, a0.y + xr0.y); p = fmaf(tt.y, LRELU(f), p);
            f = fmaf(ea, w.z, a0.z + xr0.z); p = fmaf(tt.z, LRELU(f), p);
            f = fmaf(ea, w.w, a0.w + xr0.w); p = fmaf(tt.w, LRELU(f), p);
            w = pWe[1]; tt = pAt[1];
            f = fmaf(ea, w.x, a1.x + xr1.x); p = fmaf(tt.x, LRELU(f), p);
            f = fmaf(ea, w.y, a1.y + xr1.y); p = fmaf(tt.y, LRELU(f), p);
            f = fmaf(ea, w.z, a1.z + xr1.z); p = fmaf(tt.z, LRELU(f), p);
            f = fmaf(ea, w.w, a1.w + xr1.w); p = fmaf(tt.w, LRELU(f), p);
#undef LRELU
        }
        p += __shfl_xor_sync(0xffffffffu, p, 1);   // combine dim-halves
        if (act) {
            if (half == 0) {
                if (use_buf) psc[ei * 4 + h] = p;   // 16 lanes, distinct banks
                else         g_score[(long long)e * 4 + h] = p;
            }
        } else {
            p = NEG_INF;
        }
        // batch max over the 4 edge slots of this (head,half)
        float q = fmaxf(p, __shfl_xor_sync(0xffffffffu, p, 8));
        q = fmaxf(q, __shfl_xor_sync(0xffffffffu, q, 16));
        float mnew = fmaxf(m, q);
        float scale = __expf(m - mnew);             // first batch: exp(-inf)=0
        float ex = act ? __expf(p - mnew) : 0.f;
        den = den * scale + ex;
        acc[0] = fmaf(acc[0], scale, ex * a0.x);
        acc[1] = fmaf(acc[1], scale, ex * a0.y);
        acc[2] = fmaf(acc[2], scale, ex * a0.z);
        acc[3] = fmaf(acc[3], scale, ex * a0.w);
        acc[4] = fmaf(acc[4], scale, ex * a1.x);
        acc[5] = fmaf(acc[5], scale, ex * a1.y);
        acc[6] = fmaf(acc[6], scale, ex * a1.z);
        acc[7] = fmaf(acc[7], scale, ex * a1.w);
        m = mnew;
    }

    // reduce across the 4 edge-slot lanes (fixed tree -> deterministic)
#pragma unroll
    for (int off = 8; off <= 16; off <<= 1) {
        den += __shfl_xor_sync(0xffffffffu, den, off);
#pragma unroll
        for (int j = 0; j < 8; j++)
            acc[j] += __shfl_xor_sync(0xffffffffu, acc[j], off);
    }

    if (eslot == 0) {
#pragma unroll
        for (int j = 0; j < 8; j++) sacc[warp][dbase + j] = acc[j];
    }
    __syncwarp();
    float2 av = *(const float2*)&sacc[warp][lane * 2];

    float deng = __shfl_sync(0xffffffffu, den, (lane >> 3) * 2);
    float dfin = deng + 1e-16f;
    float2 r2  = *(const float2*)&g_res[n * 64 + lane * 2];
    float2 bo2 = *(const float2*)&bias_out[lane * 2];
    float ox = av.x / dfin + bo2.x + r2.x;
    float oy = av.y / dfin + bo2.y + r2.y;
    ox = ox > 0.f ? ox : expm1f(ox);
    oy = oy > 0.f ? oy : expm1f(oy);
    *(float2*)&out[n * 64 + lane * 2] = make_float2(ox, oy);

    if (lane == 0) g_deg[n] = 0;   // reset for next call

    if (do_alpha) {
        float m0 = __shfl_sync(0xffffffffu, m, 0);
        float m1 = __shfl_sync(0xffffffffu, m, 2);
        float m2 = __shfl_sync(0xffffffffu, m, 4);
        float m3 = __shfl_sync(0xffffffffu, m, 6);
        float d0 = __shfl_sync(0xffffffffu, den, 0) + 1e-16f;
        float d1 = __shfl_sync(0xffffffffu, den, 2) + 1e-16f;
        float d2 = __shfl_sync(0xffffffffu, den, 4) + 1e-16f;
        float d3 = __shfl_sync(0xffffffffu, den, 6) + 1e-16f;
        for (int i = lane; i < deg; i += 32) {
            int e = use_buf ? buf[i] : g_elist[start + i];
            float4 s4 = use_buf ? *(const float4*)&psc[i * 4]
                                : *(const float4*)&g_score[(long long)e * 4];
            float4 a;
            a.x = __expf(s4.x - m0) / d0;
            a.y = __expf(s4.y - m1) / d1;
            a.z = __expf(s4.z - m2) / d2;
            a.w = __expf(s4.w - m3) / d3;
            *(float4*)&out[AL_OFF + (long long)e * 4] = a;
        }
    }
}

// ---------------- launch: single stream, two kernels ----------------
extern "C" void kernel_launch(void* const* d_in, const int* in_sizes, int n_in,
                              void* d_out, int out_size) {
    const float* x         = (const float*)d_in[0];
    const int*   ei        = (const int*)d_in[1];
    const float* edge_attr = (const float*)d_in[2];
    const float* Wl        = (const float*)d_in[3];
    const float* bl        = (const float*)d_in[4];
    const float* Wr        = (const float*)d_in[5];
    const float* br        = (const float*)d_in[6];
    const float* We        = (const float*)d_in[7];
    const float* att       = (const float*)d_in[8];
    const float* bias_out  = (const float*)d_in[9];
    const float* Wres      = (const float*)d_in[10];
    const float* bres      = (const float*)d_in[11];
    float* out = (float*)d_out;

    int write_ei = (out_size >= 4800000);
    int do_alpha = (out_size >= 8000000);

    k_front<<<FRONTGRID, 256>>>(ei, x, Wl, bl, Wr, br, Wres, bres, out, write_ei);
    k_node<<<NN / 4, 128>>>(edge_attr, We, att, bias_out, out, do_alpha);
}